// round 4
// baseline (speedup 1.0000x reference)
#include <cuda_runtime.h>
#include <cuda_bf16.h>
#include <math.h>

#define NN 100000
#define NE 1600000
#define DF 256
#define NBLK ((NN + 255) / 256)   // 391

// ---------------- scratch (static device globals; no allocation) ----------------
__device__ int   g_deg[NN];
__device__ float g_invdeg[NN];
__device__ int   g_rowptr[NN + 1];
__device__ int   g_cursor[NN];
__device__ int   g_blksum[512];
__device__ int   g_esrc[NE];
__device__ float g_neigh[(size_t)NN * DF];   // neigh1, then reused as neigh2
__device__ float g_h[(size_t)NN * DF];       // layer-1 activations

// ---------------- degree + CSR build ----------------
__global__ void k_zero_deg() {
    int i = blockIdx.x * 256 + threadIdx.x;
    if (i < NN) g_deg[i] = 0;
}

__global__ void k_hist(const int* __restrict__ dst) {
    int e = blockIdx.x * 256 + threadIdx.x;
    if (e < NE) atomicAdd(&g_deg[dst[e]], 1);
}

// per-256-block exclusive scan of deg into rowptr (local), block sums to g_blksum
__global__ void k_scanA() {
    __shared__ int sh[256];
    int b = blockIdx.x, t = threadIdx.x;
    int i = b * 256 + t;
    int v = (i < NN) ? g_deg[i] : 0;
    sh[t] = v;
    __syncthreads();
#pragma unroll
    for (int o = 1; o < 256; o <<= 1) {
        int x = (t >= o) ? sh[t - o] : 0;
        __syncthreads();
        sh[t] += x;
        __syncthreads();
    }
    if (i < NN) g_rowptr[i] = sh[t] - v;   // local exclusive
    if (t == 255) g_blksum[b] = sh[255];   // block total
}

// single-block exclusive scan of the 391 block sums
__global__ void k_scanB(int nblk) {
    __shared__ int sh[512];
    int t = threadIdx.x;
    int v = (t < nblk) ? g_blksum[t] : 0;
    sh[t] = v;
    __syncthreads();
#pragma unroll
    for (int o = 1; o < 512; o <<= 1) {
        int x = (t >= o) ? sh[t - o] : 0;
        __syncthreads();
        sh[t] += x;
        __syncthreads();
    }
    if (t < nblk) g_blksum[t] = sh[t] - v; // exclusive
}

// add block offsets -> global rowptr, init cursors, compute 1/max(deg,1)
__global__ void k_scanC() {
    int b = blockIdx.x, t = threadIdx.x;
    int i = b * 256 + t;
    if (i < NN) {
        int r = g_rowptr[i] + g_blksum[b];
        g_rowptr[i] = r;
        g_cursor[i] = r;
        int d = g_deg[i];
        g_invdeg[i] = 1.0f / (float)(d > 1 ? d : 1);
    }
    if (i == 0) g_rowptr[NN] = NE;
}

__global__ void k_scatter(const int* __restrict__ src, const int* __restrict__ dst) {
    int e = blockIdx.x * 256 + threadIdx.x;
    if (e < NE) {
        int d = dst[e];
        int p = atomicAdd(&g_cursor[d], 1);
        g_esrc[p] = src[e];
    }
}

// ---------------- mean aggregation (gather over CSR) ----------------
// block = (64,4): 4 nodes/block, 64 threads per node, float4 per thread (256 floats/row)
__device__ __forceinline__ void agg_body(const float4* __restrict__ feat,
                                         float4* __restrict__ outbuf) {
    int node = blockIdx.x * 4 + threadIdx.y;
    if (node >= NN) return;
    int t = threadIdx.x;
    int beg = g_rowptr[node];
    int end = g_rowptr[node + 1];
    float4 acc = make_float4(0.f, 0.f, 0.f, 0.f);
    int e = beg;
    for (; e + 1 < end; e += 2) {
        int s0 = g_esrc[e];
        int s1 = g_esrc[e + 1];
        float4 v0 = feat[(size_t)s0 * 64 + t];
        float4 v1 = feat[(size_t)s1 * 64 + t];
        acc.x += v0.x + v1.x;
        acc.y += v0.y + v1.y;
        acc.z += v0.z + v1.z;
        acc.w += v0.w + v1.w;
    }
    if (e < end) {
        int s0 = g_esrc[e];
        float4 v0 = feat[(size_t)s0 * 64 + t];
        acc.x += v0.x; acc.y += v0.y; acc.z += v0.z; acc.w += v0.w;
    }
    float id = g_invdeg[node];
    acc.x *= id; acc.y *= id; acc.z *= id; acc.w *= id;
    outbuf[(size_t)node * 64 + t] = acc;
}

__global__ void k_agg1(const float* __restrict__ x) {
    agg_body((const float4*)x, (float4*)g_neigh);
}

__global__ void k_agg2() {
    agg_body((const float4*)g_h, (float4*)g_neigh);
}

// ---------------- layer-1 fused GEMM + bias + sigmoid ----------------
// C[100000,256] = X@Wself + NEIGH@Wneigh + b, sigmoid -> g_h
// tiles: BM=128, BN=128, BK=8, 256 threads, 8x8 per thread, K_total=512 (concat)
__global__ __launch_bounds__(256) void k_gemm1(const float* __restrict__ X,
                                               const float* __restrict__ Ws,
                                               const float* __restrict__ Wn,
                                               const float* __restrict__ bias) {
    __shared__ float As[8][128];
    __shared__ float Bs[8][128];

    int tid  = threadIdx.x;
    int brow = blockIdx.y * 128;
    int bcol = blockIdx.x * 128;
    int ty = tid >> 4;        // 0..15
    int tx = tid & 15;        // 0..15

    int arow  = tid >> 1;         // 0..127
    int acol4 = (tid & 1) * 4;    // 0 or 4
    int bkr   = tid >> 5;         // 0..7
    int bc4   = (tid & 31) * 4;   // 0..124

    float acc[8][8];
#pragma unroll
    for (int i = 0; i < 8; i++)
#pragma unroll
        for (int j = 0; j < 8; j++) acc[i][j] = 0.f;

    for (int kt = 0; kt < 64; ++kt) {
        int k0 = kt * 8;
        const float* A = (k0 < 256) ? X : g_neigh;
        const float* B = (k0 < 256) ? Ws : Wn;
        int ka = (k0 < 256) ? k0 : (k0 - 256);

        // load A tile (128 x 8)
        int gr = brow + arow;
        float4 av = make_float4(0.f, 0.f, 0.f, 0.f);
        if (gr < NN)
            av = *(const float4*)(A + (size_t)gr * 256 + ka + acol4);
        As[acol4 + 0][arow] = av.x;
        As[acol4 + 1][arow] = av.y;
        As[acol4 + 2][arow] = av.z;
        As[acol4 + 3][arow] = av.w;

        // load B tile (8 x 128); W is [256,256] row-major, always in-bounds
        float4 bv = *(const float4*)(B + (size_t)(ka + bkr) * 256 + bcol + bc4);
        *(float4*)&Bs[bkr][bc4] = bv;

        __syncthreads();

#pragma unroll
        for (int k = 0; k < 8; ++k) {
            float a[8], bb[8];
#pragma unroll
            for (int j = 0; j < 8; j++) a[j] = As[k][ty * 8 + j];
#pragma unroll
            for (int j = 0; j < 8; j++) bb[j] = Bs[k][tx * 8 + j];
#pragma unroll
            for (int i = 0; i < 8; i++)
#pragma unroll
                for (int j = 0; j < 8; j++) acc[i][j] += a[i] * bb[j];
        }
        __syncthreads();
    }

    // epilogue: bias + sigmoid
#pragma unroll
    for (int i = 0; i < 8; i++) {
        int r = brow + ty * 8 + i;
        if (r >= NN) continue;
#pragma unroll
        for (int j = 0; j < 8; j++) {
            int c = bcol + tx * 8 + j;
            float v = acc[i][j] + bias[c];
            g_h[(size_t)r * 256 + c] = 1.0f / (1.0f + __expf(-v));
        }
    }
}

// ---------------- layer 2: two 256-dot-products per node ----------------
__global__ __launch_bounds__(256) void k_layer2(const float* __restrict__ Ws2,
                                                const float* __restrict__ Wn2,
                                                const float* __restrict__ b2,
                                                float* __restrict__ out) {
    __shared__ float ws[256], wn[256];
    int t = threadIdx.x;
    ws[t] = Ws2[t];
    wn[t] = Wn2[t];
    __syncthreads();

    int warp = t >> 5, lane = t & 31;
    int node = blockIdx.x * 8 + warp;
    if (node >= NN) return;

    const float* hr = g_h + (size_t)node * 256;
    const float* nr = g_neigh + (size_t)node * 256;
    float s = 0.f;
#pragma unroll
    for (int j = lane; j < 256; j += 32)
        s += hr[j] * ws[j] + nr[j] * wn[j];
#pragma unroll
    for (int o = 16; o > 0; o >>= 1)
        s += __shfl_down_sync(0xffffffffu, s, o);
    if (lane == 0) out[node] = s + b2[0];
}

// ---------------- launch ----------------
extern "C" void kernel_launch(void* const* d_in, const int* in_sizes, int n_in,
                              void* d_out, int out_size) {
    const float* x   = (const float*)d_in[0];
    const int*   src = (const int*)d_in[1];
    const int*   dst = (const int*)d_in[2];
    const float* Ws1 = (const float*)d_in[3];
    const float* Wn1 = (const float*)d_in[4];
    const float* b1  = (const float*)d_in[5];
    const float* Ws2 = (const float*)d_in[6];
    const float* Wn2 = (const float*)d_in[7];
    const float* b2  = (const float*)d_in[8];
    float* out = (float*)d_out;

    int edgeBlocks = (NE + 255) / 256;

    // CSR build
    k_zero_deg<<<NBLK, 256>>>();
    k_hist<<<edgeBlocks, 256>>>(dst);
    k_scanA<<<NBLK, 256>>>();
    k_scanB<<<1, 512>>>(NBLK);
    k_scanC<<<NBLK, 256>>>();
    k_scatter<<<edgeBlocks, 256>>>(src, dst);

    // layer 1
    k_agg1<<<(NN + 3) / 4, dim3(64, 4)>>>(x);
    k_gemm1<<<dim3(2, (NN + 127) / 128), 256>>>(x, Ws1, Wn1, b1);

    // layer 2
    k_agg2<<<(NN + 3) / 4, dim3(64, 4)>>>();
    k_layer2<<<(NN + 7) / 8, 256>>>(Ws2, Wn2, b2, out);
}

// round 5
// speedup vs baseline: 1.4124x; 1.4124x over previous
#include <cuda_runtime.h>
#include <cuda_bf16.h>
#include <math.h>

#define NN 100000
#define NE 1600000
#define DF 256
#define NBLK ((NN + 255) / 256)   // 391

// ---------------- scratch (static device globals; no allocation) ----------------
__device__ int   g_deg[NN];
__device__ float g_invdeg[NN];
__device__ int   g_rowptr[NN + 1];
__device__ int   g_cursor[NN];
__device__ int   g_blksum[512];
__device__ int   g_esrc[NE];
__device__ float g_neigh[(size_t)NN * DF];   // neigh1
__device__ float g_h[(size_t)NN * DF];       // layer-1 activations
__device__ float g_p[NN];                    // h . Wn2  (per node)
__device__ float g_q[NN];                    // h . Ws2 + b2

// ---------------- f32x2 helpers ----------------
__device__ __forceinline__ unsigned long long pack2(float lo, float hi) {
    unsigned long long r;
    asm("mov.b64 %0, {%1, %2};" : "=l"(r) : "f"(lo), "f"(hi));
    return r;
}
__device__ __forceinline__ void unpack2(unsigned long long v, float& lo, float& hi) {
    asm("mov.b64 {%0, %1}, %2;" : "=f"(lo), "=f"(hi) : "l"(v));
}
__device__ __forceinline__ void ffma2(unsigned long long& d,
                                      unsigned long long a, unsigned long long b) {
    asm("fma.rn.f32x2 %0, %1, %2, %0;" : "+l"(d) : "l"(a), "l"(b));
}

// ---------------- degree + CSR build ----------------
__global__ void k_zero_deg() {
    int i = blockIdx.x * 256 + threadIdx.x;
    if (i < NN) g_deg[i] = 0;
}

__global__ void k_hist(const int* __restrict__ dst) {
    int e = blockIdx.x * 256 + threadIdx.x;
    if (e < NE) atomicAdd(&g_deg[dst[e]], 1);
}

__global__ void k_scanA() {
    __shared__ int sh[256];
    int b = blockIdx.x, t = threadIdx.x;
    int i = b * 256 + t;
    int v = (i < NN) ? g_deg[i] : 0;
    sh[t] = v;
    __syncthreads();
#pragma unroll
    for (int o = 1; o < 256; o <<= 1) {
        int x = (t >= o) ? sh[t - o] : 0;
        __syncthreads();
        sh[t] += x;
        __syncthreads();
    }
    if (i < NN) g_rowptr[i] = sh[t] - v;
    if (t == 255) g_blksum[b] = sh[255];
}

__global__ void k_scanB(int nblk) {
    __shared__ int sh[512];
    int t = threadIdx.x;
    int v = (t < nblk) ? g_blksum[t] : 0;
    sh[t] = v;
    __syncthreads();
#pragma unroll
    for (int o = 1; o < 512; o <<= 1) {
        int x = (t >= o) ? sh[t - o] : 0;
        __syncthreads();
        sh[t] += x;
        __syncthreads();
    }
    if (t < nblk) g_blksum[t] = sh[t] - v;
}

__global__ void k_scanC() {
    int b = blockIdx.x, t = threadIdx.x;
    int i = b * 256 + t;
    if (i < NN) {
        int r = g_rowptr[i] + g_blksum[b];
        g_rowptr[i] = r;
        g_cursor[i] = r;
        int d = g_deg[i];
        g_invdeg[i] = 1.0f / (float)(d > 1 ? d : 1);
    }
    if (i == 0) g_rowptr[NN] = NE;
}

__global__ void k_scatter(const int* __restrict__ src, const int* __restrict__ dst) {
    int e = blockIdx.x * 256 + threadIdx.x;
    if (e < NE) {
        int d = dst[e];
        int p = atomicAdd(&g_cursor[d], 1);
        g_esrc[p] = src[e];
    }
}

// ---------------- mean aggregation (gather over CSR), 4-wide MLP ----------------
__global__ void k_agg1(const float* __restrict__ x) {
    const float4* __restrict__ feat = (const float4*)x;
    float4* __restrict__ outbuf = (float4*)g_neigh;
    int node = blockIdx.x * 4 + threadIdx.y;
    if (node >= NN) return;
    int t = threadIdx.x;
    int beg = g_rowptr[node];
    int end = g_rowptr[node + 1];
    float4 acc = make_float4(0.f, 0.f, 0.f, 0.f);
    int e = beg;
    for (; e + 3 < end; e += 4) {
        int s0 = g_esrc[e];
        int s1 = g_esrc[e + 1];
        int s2 = g_esrc[e + 2];
        int s3 = g_esrc[e + 3];
        float4 v0 = feat[(size_t)s0 * 64 + t];
        float4 v1 = feat[(size_t)s1 * 64 + t];
        float4 v2 = feat[(size_t)s2 * 64 + t];
        float4 v3 = feat[(size_t)s3 * 64 + t];
        acc.x += (v0.x + v1.x) + (v2.x + v3.x);
        acc.y += (v0.y + v1.y) + (v2.y + v3.y);
        acc.z += (v0.z + v1.z) + (v2.z + v3.z);
        acc.w += (v0.w + v1.w) + (v2.w + v3.w);
    }
    for (; e < end; ++e) {
        int s0 = g_esrc[e];
        float4 v0 = feat[(size_t)s0 * 64 + t];
        acc.x += v0.x; acc.y += v0.y; acc.z += v0.z; acc.w += v0.w;
    }
    float id = g_invdeg[node];
    acc.x *= id; acc.y *= id; acc.z *= id; acc.w *= id;
    outbuf[(size_t)node * 64 + t] = acc;
}

// ---------------- layer-1 fused GEMM + bias + sigmoid (FFMA2) ----------------
// C[100000,256] = X@Ws + NEIGH@Wn + b, sigmoid -> g_h
// BM=128, BN=128, BK=8, 256 threads, 8x8 per thread (packed as 8x4 f32x2)
__global__ __launch_bounds__(256) void k_gemm1(const float* __restrict__ X,
                                               const float* __restrict__ Ws,
                                               const float* __restrict__ Wn,
                                               const float* __restrict__ bias) {
    __shared__ float As[8][128];
    __shared__ float Bs[8][128];

    int tid  = threadIdx.x;
    int brow = blockIdx.y * 128;
    int bcol = blockIdx.x * 128;
    int ty = tid >> 4;        // 0..15
    int tx = tid & 15;        // 0..15

    int arow  = tid >> 1;         // 0..127
    int acol4 = (tid & 1) * 4;    // 0 or 4
    int bkr   = tid >> 5;         // 0..7
    int bc4   = (tid & 31) * 4;   // 0..124

    unsigned long long acc[8][4];
#pragma unroll
    for (int i = 0; i < 8; i++)
#pragma unroll
        for (int j = 0; j < 4; j++) acc[i][j] = 0ull;

    int gr = brow + arow;
    bool inb = (gr < NN);

#pragma unroll 1
    for (int phase = 0; phase < 2; ++phase) {
        const float* A = phase ? g_neigh : X;
        const float* B = phase ? Wn : Ws;
#pragma unroll 1
        for (int kt = 0; kt < 32; ++kt) {
            int ka = kt * 8;

            // load A tile (128 x 8)
            float4 av = make_float4(0.f, 0.f, 0.f, 0.f);
            if (inb)
                av = *(const float4*)(A + (size_t)gr * 256 + ka + acol4);
            As[acol4 + 0][arow] = av.x;
            As[acol4 + 1][arow] = av.y;
            As[acol4 + 2][arow] = av.z;
            As[acol4 + 3][arow] = av.w;

            // load B tile (8 x 128)
            float4 bv = *(const float4*)(B + (size_t)(ka + bkr) * 256 + bcol + bc4);
            *(float4*)&Bs[bkr][bc4] = bv;

            __syncthreads();

#pragma unroll
            for (int k = 0; k < 8; ++k) {
                float4 a0 = *(const float4*)&As[k][ty * 8];
                float4 a1 = *(const float4*)&As[k][ty * 8 + 4];
                const unsigned long long* Bp =
                    (const unsigned long long*)&Bs[k][tx * 8];
                unsigned long long bp0 = Bp[0];
                unsigned long long bp1 = Bp[1];
                unsigned long long bp2 = Bp[2];
                unsigned long long bp3 = Bp[3];
                float av8[8] = {a0.x, a0.y, a0.z, a0.w, a1.x, a1.y, a1.z, a1.w};
#pragma unroll
                for (int i = 0; i < 8; ++i) {
                    unsigned long long ai = pack2(av8[i], av8[i]);
                    ffma2(acc[i][0], ai, bp0);
                    ffma2(acc[i][1], ai, bp1);
                    ffma2(acc[i][2], ai, bp2);
                    ffma2(acc[i][3], ai, bp3);
                }
            }
            __syncthreads();
        }
    }

    // epilogue: bias + sigmoid
#pragma unroll
    for (int i = 0; i < 8; i++) {
        int r = brow + ty * 8 + i;
        if (r >= NN) continue;
#pragma unroll
        for (int j = 0; j < 4; j++) {
            int c = bcol + tx * 8 + j * 2;
            float lo, hi;
            unpack2(acc[i][j], lo, hi);
            float v0 = lo + bias[c];
            float v1 = hi + bias[c + 1];
            float2 o;
            o.x = 1.0f / (1.0f + __expf(-v0));
            o.y = 1.0f / (1.0f + __expf(-v1));
            *(float2*)(g_h + (size_t)r * 256 + c) = o;
        }
    }
}

// ---------------- layer 2a: per-node dots  p = h.Wn2, q = h.Ws2 + b2 ----------------
__global__ __launch_bounds__(256) void k_dot(const float* __restrict__ Ws2,
                                             const float* __restrict__ Wn2,
                                             const float* __restrict__ b2) {
    __shared__ float ws[256], wn[256];
    int t = threadIdx.x;
    ws[t] = Ws2[t];
    wn[t] = Wn2[t];
    __syncthreads();

    int warp = t >> 5, lane = t & 31;
    int node = blockIdx.x * 8 + warp;
    if (node >= NN) return;

    const float* hr = g_h + (size_t)node * 256;
    float sq = 0.f, sp = 0.f;
#pragma unroll
    for (int j = lane; j < 256; j += 32) {
        float h = hr[j];
        sq += h * ws[j];
        sp += h * wn[j];
    }
#pragma unroll
    for (int o = 16; o > 0; o >>= 1) {
        sq += __shfl_down_sync(0xffffffffu, sq, o);
        sp += __shfl_down_sync(0xffffffffu, sp, o);
    }
    if (lane == 0) {
        g_q[node] = sq + b2[0];
        g_p[node] = sp;
    }
}

// ---------------- layer 2b: scalar mean-aggregate + add ----------------
__global__ void k_agg_scalar(float* __restrict__ out) {
    int n = blockIdx.x * 256 + threadIdx.x;
    if (n >= NN) return;
    int beg = g_rowptr[n];
    int end = g_rowptr[n + 1];
    float s0 = 0.f, s1 = 0.f, s2 = 0.f, s3 = 0.f;
    int e = beg;
    for (; e + 3 < end; e += 4) {
        s0 += g_p[g_esrc[e]];
        s1 += g_p[g_esrc[e + 1]];
        s2 += g_p[g_esrc[e + 2]];
        s3 += g_p[g_esrc[e + 3]];
    }
    for (; e < end; ++e) s0 += g_p[g_esrc[e]];
    float s = (s0 + s1) + (s2 + s3);
    out[n] = g_q[n] + s * g_invdeg[n];
}

// ---------------- launch ----------------
extern "C" void kernel_launch(void* const* d_in, const int* in_sizes, int n_in,
                              void* d_out, int out_size) {
    const float* x   = (const float*)d_in[0];
    const int*   src = (const int*)d_in[1];
    const int*   dst = (const int*)d_in[2];
    const float* Ws1 = (const float*)d_in[3];
    const float* Wn1 = (const float*)d_in[4];
    const float* b1  = (const float*)d_in[5];
    const float* Ws2 = (const float*)d_in[6];
    const float* Wn2 = (const float*)d_in[7];
    const float* b2  = (const float*)d_in[8];
    float* out = (float*)d_out;

    int edgeBlocks = (NE + 255) / 256;

    // CSR build
    k_zero_deg<<<NBLK, 256>>>();
    k_hist<<<edgeBlocks, 256>>>(dst);
    k_scanA<<<NBLK, 256>>>();
    k_scanB<<<1, 512>>>(NBLK);
    k_scanC<<<NBLK, 256>>>();
    k_scatter<<<edgeBlocks, 256>>>(src, dst);

    // layer 1
    k_agg1<<<(NN + 3) / 4, dim3(64, 4)>>>(x);
    k_gemm1<<<dim3(2, (NN + 127) / 128), 256>>>(x, Ws1, Wn1, b1);

    // layer 2 (linearity: aggregate scalars, not features)
    k_dot<<<(NN + 7) / 8, 256>>>(Ws2, Wn2, b2);
    k_agg_scalar<<<NBLK, 256>>>(out);
}

// round 8
// speedup vs baseline: 1.9818x; 1.4032x over previous
#include <cuda_runtime.h>
#include <cuda_bf16.h>
#include <math.h>
#include <stdint.h>

#define NN 100000
#define NE 1600000
#define DF 256
#define NBLK ((NN + 255) / 256)   // 391

// ---------------- scratch (static device globals; no allocation) ----------------
__device__ int   g_deg[NN];
__device__ float g_invdeg[NN];
__device__ int   g_rowptr[NN + 1];
__device__ int   g_cursor[NN];
__device__ int   g_blksum[512];
__device__ int   g_esrc[NE];
__device__ float g_neigh[(size_t)NN * DF];   // neigh1
__device__ float g_p[NN];                    // h . Wn2  (atomically accumulated)
__device__ float g_q[NN];                    // h . Ws2  (atomically accumulated)
__device__ __nv_bfloat16 g_wt_hi[512 * 256]; // [K=512][N=256] row-major, hi split
__device__ __nv_bfloat16 g_wt_lo[512 * 256]; // lo split

// ---------------- helpers ----------------
__device__ __forceinline__ uint32_t s2u(const void* p) {
    uint32_t a;
    asm("{ .reg .u64 t; cvta.to.shared.u64 t, %1; cvt.u32.u64 %0, t; }"
        : "=r"(a) : "l"(p));
    return a;
}

__device__ __forceinline__ uint32_t pk(__nv_bfloat16 a, __nv_bfloat16 b) {
    __nv_bfloat162 t = __halves2bfloat162(a, b);
    return *reinterpret_cast<uint32_t*>(&t);
}

#define LDSM4(r, addr) \
    asm volatile("ldmatrix.sync.aligned.m8n8.x4.shared.b16 {%0,%1,%2,%3}, [%4];" \
        : "=r"((r)[0]), "=r"((r)[1]), "=r"((r)[2]), "=r"((r)[3]) : "r"(addr))

#define LDSM4T(r, addr) \
    asm volatile("ldmatrix.sync.aligned.m8n8.x4.trans.shared.b16 {%0,%1,%2,%3}, [%4];" \
        : "=r"((r)[0]), "=r"((r)[1]), "=r"((r)[2]), "=r"((r)[3]) : "r"(addr))

__device__ __forceinline__ void mma16816(float* c, const uint32_t* a, const uint32_t* b) {
    asm volatile(
        "mma.sync.aligned.m16n8k16.row.col.f32.bf16.bf16.f32 "
        "{%0,%1,%2,%3}, {%4,%5,%6,%7}, {%8,%9}, {%0,%1,%2,%3};"
        : "+f"(c[0]), "+f"(c[1]), "+f"(c[2]), "+f"(c[3])
        : "r"(a[0]), "r"(a[1]), "r"(a[2]), "r"(a[3]), "r"(b[0]), "r"(b[1]));
}

// ---------------- init / CSR build ----------------
__global__ void k_init() {
    int i = blockIdx.x * 256 + threadIdx.x;
    if (i < NN) {
        g_deg[i] = 0;
        g_p[i] = 0.f;
        g_q[i] = 0.f;
    }
}

__global__ void k_hist(const int* __restrict__ dst) {
    int e = blockIdx.x * 256 + threadIdx.x;
    if (e < NE) atomicAdd(&g_deg[dst[e]], 1);
}

__global__ void k_scanA() {
    __shared__ int sh[256];
    int b = blockIdx.x, t = threadIdx.x;
    int i = b * 256 + t;
    int v = (i < NN) ? g_deg[i] : 0;
    sh[t] = v;
    __syncthreads();
#pragma unroll
    for (int o = 1; o < 256; o <<= 1) {
        int x = (t >= o) ? sh[t - o] : 0;
        __syncthreads();
        sh[t] += x;
        __syncthreads();
    }
    if (i < NN) g_rowptr[i] = sh[t] - v;
    if (t == 255) g_blksum[b] = sh[255];
}

__global__ void k_scanB(int nblk) {
    __shared__ int sh[512];
    int t = threadIdx.x;
    int v = (t < nblk) ? g_blksum[t] : 0;
    sh[t] = v;
    __syncthreads();
#pragma unroll
    for (int o = 1; o < 512; o <<= 1) {
        int x = (t >= o) ? sh[t - o] : 0;
        __syncthreads();
        sh[t] += x;
        __syncthreads();
    }
    if (t < nblk) g_blksum[t] = sh[t] - v;
}

__global__ void k_scanC() {
    int b = blockIdx.x, t = threadIdx.x;
    int i = b * 256 + t;
    if (i < NN) {
        int r = g_rowptr[i] + g_blksum[b];
        g_rowptr[i] = r;
        g_cursor[i] = r;
        int d = g_deg[i];
        g_invdeg[i] = 1.0f / (float)(d > 1 ? d : 1);
    }
    if (i == 0) g_rowptr[NN] = NE;
}

__global__ void k_scatter(const int* __restrict__ src, const int* __restrict__ dst) {
    int e = blockIdx.x * 256 + threadIdx.x;
    if (e < NE) {
        int d = dst[e];
        int p = atomicAdd(&g_cursor[d], 1);
        g_esrc[p] = src[e];
    }
}

// ---------------- mean aggregation (gather over CSR) ----------------
__global__ void k_agg1(const float* __restrict__ x) {
    const float4* __restrict__ feat = (const float4*)x;
    float4* __restrict__ outbuf = (float4*)g_neigh;
    int node = blockIdx.x * 4 + threadIdx.y;
    if (node >= NN) return;
    int t = threadIdx.x;
    int beg = g_rowptr[node];
    int end = g_rowptr[node + 1];
    float4 acc = make_float4(0.f, 0.f, 0.f, 0.f);
    int e = beg;
    for (; e + 3 < end; e += 4) {
        int s0 = g_esrc[e];
        int s1 = g_esrc[e + 1];
        int s2 = g_esrc[e + 2];
        int s3 = g_esrc[e + 3];
        float4 v0 = feat[(size_t)s0 * 64 + t];
        float4 v1 = feat[(size_t)s1 * 64 + t];
        float4 v2 = feat[(size_t)s2 * 64 + t];
        float4 v3 = feat[(size_t)s3 * 64 + t];
        acc.x += (v0.x + v1.x) + (v2.x + v3.x);
        acc.y += (v0.y + v1.y) + (v2.y + v3.y);
        acc.z += (v0.z + v1.z) + (v2.z + v3.z);
        acc.w += (v0.w + v1.w) + (v2.w + v3.w);
    }
    for (; e < end; ++e) {
        int s0 = g_esrc[e];
        float4 v0 = feat[(size_t)s0 * 64 + t];
        acc.x += v0.x; acc.y += v0.y; acc.z += v0.z; acc.w += v0.w;
    }
    float id = g_invdeg[node];
    acc.x *= id; acc.y *= id; acc.z *= id; acc.w *= id;
    outbuf[(size_t)node * 64 + t] = acc;
}

// ---------------- weight prep: [K=512][N=256] bf16 hi/lo split ----------------
__global__ void k_prepw(const float* __restrict__ Ws, const float* __restrict__ Wn) {
    int idx = blockIdx.x * 256 + threadIdx.x;   // 512 blocks
    int k = idx >> 8;
    int n = idx & 255;
    float w = (k < 256) ? Ws[(size_t)k * 256 + n] : Wn[(size_t)(k - 256) * 256 + n];
    __nv_bfloat16 hi = __float2bfloat16(w);
    __nv_bfloat16 lo = __float2bfloat16(w - __bfloat162float(hi));
    g_wt_hi[idx] = hi;
    g_wt_lo[idx] = lo;
}

// ---------------- layer-1 GEMM (mma.sync bf16 hi/lo) + fused layer-2 dots ----------------
// C[row, col] = sigmoid([X|NEIGH] @ Wt + b); q[row] += C·Ws2, p[row] += C·Wn2
// CTA: 128 rows x 128 cols; 8 warps: wm = wid&3 (32 rows), wn = wid>>2 (64 cols)
#define AST 40    // As row stride (bf16) : conflict-free ldmatrix
#define BST 136   // Bs row stride (bf16)

__global__ __launch_bounds__(256) void k_gemm_mma(const float* __restrict__ X,
                                                  const float* __restrict__ bias,
                                                  const float* __restrict__ Ws2,
                                                  const float* __restrict__ Wn2) {
    __shared__ __nv_bfloat16 As_hi[128 * AST];
    __shared__ __nv_bfloat16 As_lo[128 * AST];
    __shared__ __nv_bfloat16 Bs_hi[32 * BST];
    __shared__ __nv_bfloat16 Bs_lo[32 * BST];
    __shared__ float sb_bias[128], sb_ws[128], sb_wn[128];

    int tid = threadIdx.x;
    int wid = tid >> 5, lane = tid & 31;
    int brow = blockIdx.y * 128;
    int bcol = blockIdx.x * 128;
    int wm = wid & 3, wn = wid >> 2;

    if (tid < 128) {
        sb_bias[tid] = bias[bcol + tid];
        sb_ws[tid]   = Ws2[bcol + tid];
        sb_wn[tid]   = Wn2[bcol + tid];
    }

    float c[2][8][4];
#pragma unroll
    for (int mt = 0; mt < 2; ++mt)
#pragma unroll
        for (int nt = 0; nt < 8; ++nt)
#pragma unroll
            for (int j = 0; j < 4; ++j) c[mt][nt][j] = 0.f;

    // A load mapping: thread -> (row, 16-wide k-half)
    int arow = tid >> 1;
    int ak   = (tid & 1) * 16;
    int grow = brow + arow;
    if (grow >= NN) grow = NN - 1;

    // B load mapping: thread -> (k-row, 16-wide n-chunk); 8 thr/row x 16 = 128 cols
    int bkr = tid >> 3;
    int bnc = (tid & 7) * 16;

    uint32_t ah_base = s2u(As_hi);
    uint32_t al_base = s2u(As_lo);
    uint32_t bh_base = s2u(Bs_hi);
    uint32_t bl_base = s2u(Bs_lo);

#pragma unroll 1
    for (int ch = 0; ch < 16; ++ch) {
        int ka = ch * 32;
        const float* A = (ch < 8) ? X : (const float*)g_neigh;
        int kaa = (ch < 8) ? ka : (ka - 256);

        __syncthreads();   // previous compute done before overwriting smem

        // A chunk: 128x32 fp32 -> bf16 hi/lo
        const float4* ap = (const float4*)(A + (size_t)grow * 256 + kaa + ak);
#pragma unroll
        for (int i = 0; i < 4; ++i) {
            float4 v = ap[i];
            __nv_bfloat16 h0 = __float2bfloat16(v.x);
            __nv_bfloat16 h1 = __float2bfloat16(v.y);
            __nv_bfloat16 h2 = __float2bfloat16(v.z);
            __nv_bfloat16 h3 = __float2bfloat16(v.w);
            __nv_bfloat16 l0 = __float2bfloat16(v.x - __bfloat162float(h0));
            __nv_bfloat16 l1 = __float2bfloat16(v.y - __bfloat162float(h1));
            __nv_bfloat16 l2 = __float2bfloat16(v.z - __bfloat162float(h2));
            __nv_bfloat16 l3 = __float2bfloat16(v.w - __bfloat162float(h3));
            int off = arow * AST + ak + i * 4;
            uint2 vh, vl;
            vh.x = pk(h0, h1); vh.y = pk(h2, h3);
            vl.x = pk(l0, l1); vl.y = pk(l2, l3);
            *(uint2*)&As_hi[off] = vh;
            *(uint2*)&As_lo[off] = vl;
        }

        // B chunk: 32x128 pre-split bf16 (8 threads per k-row, 16 cols each)
        const uint4* gh = (const uint4*)(g_wt_hi + (size_t)(ka + bkr) * 256 + bcol + bnc);
        const uint4* gl = (const uint4*)(g_wt_lo + (size_t)(ka + bkr) * 256 + bcol + bnc);
#pragma unroll
        for (int i = 0; i < 2; ++i) {
            *(uint4*)&Bs_hi[bkr * BST + bnc + i * 8] = gh[i];
            *(uint4*)&Bs_lo[bkr * BST + bnc + i * 8] = gl[i];
        }

        __syncthreads();

#pragma unroll
        for (int ks = 0; ks < 2; ++ks) {
            int kk = ks * 16;
            uint32_t ah[2][4], al[2][4];
#pragma unroll
            for (int mt = 0; mt < 2; ++mt) {
                int m0 = wm * 32 + mt * 16;
                uint32_t ao = (uint32_t)((m0 + (lane & 15)) * AST + kk + (lane >> 4) * 8) * 2;
                LDSM4(ah[mt], ah_base + ao);
                LDSM4(al[mt], al_base + ao);
            }
            uint32_t bh[8][2], bl[8][2];
#pragma unroll
            for (int nq = 0; nq < 4; ++nq) {
                int n0 = wn * 64 + nq * 16;
                uint32_t bo = (uint32_t)((kk + (lane & 15)) * BST + n0 + (lane >> 4) * 8) * 2;
                uint32_t r[4];
                LDSM4T(r, bh_base + bo);
                bh[nq * 2][0] = r[0]; bh[nq * 2][1] = r[1];
                bh[nq * 2 + 1][0] = r[2]; bh[nq * 2 + 1][1] = r[3];
                LDSM4T(r, bl_base + bo);
                bl[nq * 2][0] = r[0]; bl[nq * 2][1] = r[1];
                bl[nq * 2 + 1][0] = r[2]; bl[nq * 2 + 1][1] = r[3];
            }
#pragma unroll
            for (int mt = 0; mt < 2; ++mt)
#pragma unroll
                for (int nt = 0; nt < 8; ++nt) {
                    mma16816(c[mt][nt], ah[mt], bh[nt]);
                    mma16816(c[mt][nt], ah[mt], bl[nt]);
                    mma16816(c[mt][nt], al[mt], bh[nt]);
                }
        }
    }

    // ---- fused epilogue: bias + sigmoid + dot(Ws2/Wn2) + atomic row sums ----
#pragma unroll
    for (int mt = 0; mt < 2; ++mt) {
#pragma unroll
        for (int rh = 0; rh < 2; ++rh) {
            float q = 0.f, p = 0.f;
#pragma unroll
            for (int nt = 0; nt < 8; ++nt) {
#pragma unroll
                for (int j = 0; j < 2; ++j) {
                    int lcol = wn * 64 + nt * 8 + (lane & 3) * 2 + j;
                    float v = c[mt][nt][rh * 2 + j] + sb_bias[lcol];
                    float h = 1.f / (1.f + __expf(-v));
                    q += h * sb_ws[lcol];
                    p += h * sb_wn[lcol];
                }
            }
            q += __shfl_xor_sync(0xffffffffu, q, 1);
            q += __shfl_xor_sync(0xffffffffu, q, 2);
            p += __shfl_xor_sync(0xffffffffu, p, 1);
            p += __shfl_xor_sync(0xffffffffu, p, 2);
            if ((lane & 3) == 0) {
                int row = brow + wm * 32 + mt * 16 + (lane >> 2) + rh * 8;
                if (row < NN) {
                    atomicAdd(&g_q[row], q);
                    atomicAdd(&g_p[row], p);
                }
            }
        }
    }
}

// ---------------- layer 2b: scalar mean-aggregate + combine ----------------
__global__ void k_agg_scalar(const float* __restrict__ b2, float* __restrict__ out) {
    int n = blockIdx.x * 256 + threadIdx.x;
    if (n >= NN) return;
    int beg = g_rowptr[n];
    int end = g_rowptr[n + 1];
    float s0 = 0.f, s1 = 0.f, s2 = 0.f, s3 = 0.f;
    int e = beg;
    for (; e + 3 < end; e += 4) {
        s0 += g_p[g_esrc[e]];
        s1 += g_p[g_esrc[e + 1]];
        s2 += g_p[g_esrc[e + 2]];
        s3 += g_p[g_esrc[e + 3]];
    }
    for (; e < end; ++e) s0 += g_p[g_esrc[e]];
    float s = (s0 + s1) + (s2 + s3);
    out[n] = g_q[n] + b2[0] + s * g_invdeg[n];
}

// ---------------- launch ----------------
extern "C" void kernel_launch(void* const* d_in, const int* in_sizes, int n_in,
                              void* d_out, int out_size) {
    const float* x   = (const float*)d_in[0];
    const int*   src = (const int*)d_in[1];
    const int*   dst = (const int*)d_in[2];
    const float* Ws1 = (const float*)d_in[3];
    const float* Wn1 = (const float*)d_in[4];
    const float* b1  = (const float*)d_in[5];
    const float* Ws2 = (const float*)d_in[6];
    const float* Wn2 = (const float*)d_in[7];
    const float* b2  = (const float*)d_in[8];
    float* out = (float*)d_out;

    int edgeBlocks = (NE + 255) / 256;

    // weight prep (independent of graph)
    k_prepw<<<512, 256>>>(Ws1, Wn1);

    // CSR build + zero p/q
    k_init<<<NBLK, 256>>>();
    k_hist<<<edgeBlocks, 256>>>(dst);
    k_scanA<<<NBLK, 256>>>();
    k_scanB<<<1, 512>>>(NBLK);
    k_scanC<<<NBLK, 256>>>();
    k_scatter<<<edgeBlocks, 256>>>(src, dst);

    // layer 1 aggregation
    k_agg1<<<(NN + 3) / 4, dim3(64, 4)>>>(x);

    // layer-1 GEMM + sigmoid + fused layer-2 dots
    k_gemm_mma<<<dim3(2, (NN + 127) / 128), 256>>>(x, b1, Ws2, Wn2);

    // layer 2: scalar mean-aggregate + combine
    k_agg_scalar<<<NBLK, 256>>>(b2, out);
}

// round 9
// speedup vs baseline: 2.5449x; 1.2841x over previous
#include <cuda_runtime.h>
#include <cuda_bf16.h>
#include <math.h>
#include <stdint.h>

#define NN 100000
#define NE 1600000
#define DF 256
#define NBLK ((NN + 255) / 256)   // 391

// ---------------- scratch (static device globals; no allocation) ----------------
__device__ int   g_deg[NN];
__device__ float g_invdeg[NN];
__device__ int   g_rowptr[NN + 1];
__device__ int   g_cursor[NN];
__device__ int   g_blksum[512];
__device__ int   g_esrc[NE];
__device__ float g_p[NN];
__device__ float g_q[NN];
__device__ __align__(16) __nv_bfloat16 g_x_hi[(size_t)NN * DF];
__device__ __align__(16) __nv_bfloat16 g_x_lo[(size_t)NN * DF];
__device__ __align__(16) __nv_bfloat16 g_nb_hi[(size_t)NN * DF];
__device__ __align__(16) __nv_bfloat16 g_nb_lo[(size_t)NN * DF];
__device__ __align__(16) __nv_bfloat16 g_wt_hi[512 * 256]; // [K=512][N=256]
__device__ __align__(16) __nv_bfloat16 g_wt_lo[512 * 256];

// ---------------- helpers ----------------
__device__ __forceinline__ uint32_t s2u(const void* p) {
    uint32_t a;
    asm("{ .reg .u64 t; cvta.to.shared.u64 t, %1; cvt.u32.u64 %0, t; }"
        : "=r"(a) : "l"(p));
    return a;
}

__device__ __forceinline__ uint32_t pk(__nv_bfloat16 a, __nv_bfloat16 b) {
    __nv_bfloat162 t = __halves2bfloat162(a, b);
    return *reinterpret_cast<uint32_t*>(&t);
}

__device__ __forceinline__ void cpa16(uint32_t dst, const void* src) {
    asm volatile("cp.async.cg.shared.global [%0], [%1], 16;" :: "r"(dst), "l"(src));
}
#define CP_COMMIT() asm volatile("cp.async.commit_group;" ::: "memory")
#define CP_WAIT1()  asm volatile("cp.async.wait_group 1;" ::: "memory")
#define CP_WAIT0()  asm volatile("cp.async.wait_group 0;" ::: "memory")

#define LDSM4(r, addr) \
    asm volatile("ldmatrix.sync.aligned.m8n8.x4.shared.b16 {%0,%1,%2,%3}, [%4];" \
        : "=r"((r)[0]), "=r"((r)[1]), "=r"((r)[2]), "=r"((r)[3]) : "r"(addr))

#define LDSM4T(r, addr) \
    asm volatile("ldmatrix.sync.aligned.m8n8.x4.trans.shared.b16 {%0,%1,%2,%3}, [%4];" \
        : "=r"((r)[0]), "=r"((r)[1]), "=r"((r)[2]), "=r"((r)[3]) : "r"(addr))

__device__ __forceinline__ void mma16816(float* c, const uint32_t* a, const uint32_t* b) {
    asm volatile(
        "mma.sync.aligned.m16n8k16.row.col.f32.bf16.bf16.f32 "
        "{%0,%1,%2,%3}, {%4,%5,%6,%7}, {%8,%9}, {%0,%1,%2,%3};"
        : "+f"(c[0]), "+f"(c[1]), "+f"(c[2]), "+f"(c[3])
        : "r"(a[0]), "r"(a[1]), "r"(a[2]), "r"(a[3]), "r"(b[0]), "r"(b[1]));
}

__device__ __forceinline__ void split2(float v, __nv_bfloat16& h, __nv_bfloat16& l) {
    h = __float2bfloat16(v);
    l = __float2bfloat16(v - __bfloat162float(h));
}

// ---------------- X pre-split (+ zero deg/p/q) ----------------
__global__ void k_prepx(const float* __restrict__ x) {
    int gi = blockIdx.x * 256 + threadIdx.x;        // grid = NN*64 threads
    float4 v = ((const float4*)x)[gi];
    __nv_bfloat16 h0, h1, h2, h3, l0, l1, l2, l3;
    split2(v.x, h0, l0); split2(v.y, h1, l1);
    split2(v.z, h2, l2); split2(v.w, h3, l3);
    uint2 hh, ll;
    hh.x = pk(h0, h1); hh.y = pk(h2, h3);
    ll.x = pk(l0, l1); ll.y = pk(l2, l3);
    ((uint2*)g_x_hi)[gi] = hh;
    ((uint2*)g_x_lo)[gi] = ll;
    if (gi < NN) { g_deg[gi] = 0; g_p[gi] = 0.f; g_q[gi] = 0.f; }
}

// ---------------- weight prep: [K=512][N=256] bf16 hi/lo split ----------------
__global__ void k_prepw(const float* __restrict__ Ws, const float* __restrict__ Wn) {
    int idx = blockIdx.x * 256 + threadIdx.x;   // 512 blocks
    int k = idx >> 8;
    int n = idx & 255;
    float w = (k < 256) ? Ws[(size_t)k * 256 + n] : Wn[(size_t)(k - 256) * 256 + n];
    __nv_bfloat16 hi, lo;
    split2(w, hi, lo);
    g_wt_hi[idx] = hi;
    g_wt_lo[idx] = lo;
}

// ---------------- CSR build ----------------
__global__ void k_hist(const int* __restrict__ dst) {
    int e = blockIdx.x * 256 + threadIdx.x;
    if (e < NE) atomicAdd(&g_deg[dst[e]], 1);
}

__global__ void k_scanA() {
    __shared__ int sh[256];
    int b = blockIdx.x, t = threadIdx.x;
    int i = b * 256 + t;
    int v = (i < NN) ? g_deg[i] : 0;
    sh[t] = v;
    __syncthreads();
#pragma unroll
    for (int o = 1; o < 256; o <<= 1) {
        int x = (t >= o) ? sh[t - o] : 0;
        __syncthreads();
        sh[t] += x;
        __syncthreads();
    }
    if (i < NN) g_rowptr[i] = sh[t] - v;
    if (t == 255) g_blksum[b] = sh[255];
}

__global__ void k_scanB(int nblk) {
    __shared__ int sh[512];
    int t = threadIdx.x;
    int v = (t < nblk) ? g_blksum[t] : 0;
    sh[t] = v;
    __syncthreads();
#pragma unroll
    for (int o = 1; o < 512; o <<= 1) {
        int x = (t >= o) ? sh[t - o] : 0;
        __syncthreads();
        sh[t] += x;
        __syncthreads();
    }
    if (t < nblk) g_blksum[t] = sh[t] - v;
}

__global__ void k_scanC() {
    int b = blockIdx.x, t = threadIdx.x;
    int i = b * 256 + t;
    if (i < NN) {
        int r = g_rowptr[i] + g_blksum[b];
        g_rowptr[i] = r;
        g_cursor[i] = r;
        int d = g_deg[i];
        g_invdeg[i] = 1.0f / (float)(d > 1 ? d : 1);
    }
    if (i == 0) g_rowptr[NN] = NE;
}

__global__ void k_scatter(const int* __restrict__ src, const int* __restrict__ dst) {
    int e = blockIdx.x * 256 + threadIdx.x;
    if (e < NE) {
        int d = dst[e];
        int p = atomicAdd(&g_cursor[d], 1);
        g_esrc[p] = src[e];
    }
}

// ---------------- mean aggregation -> bf16 hi/lo directly ----------------
__global__ void k_agg1(const float* __restrict__ x) {
    const float4* __restrict__ feat = (const float4*)x;
    int node = blockIdx.x * 4 + threadIdx.y;
    if (node >= NN) return;
    int t = threadIdx.x;
    int beg = g_rowptr[node];
    int end = g_rowptr[node + 1];
    float4 acc = make_float4(0.f, 0.f, 0.f, 0.f);
    int e = beg;
    for (; e + 3 < end; e += 4) {
        int s0 = g_esrc[e];
        int s1 = g_esrc[e + 1];
        int s2 = g_esrc[e + 2];
        int s3 = g_esrc[e + 3];
        float4 v0 = feat[(size_t)s0 * 64 + t];
        float4 v1 = feat[(size_t)s1 * 64 + t];
        float4 v2 = feat[(size_t)s2 * 64 + t];
        float4 v3 = feat[(size_t)s3 * 64 + t];
        acc.x += (v0.x + v1.x) + (v2.x + v3.x);
        acc.y += (v0.y + v1.y) + (v2.y + v3.y);
        acc.z += (v0.z + v1.z) + (v2.z + v3.z);
        acc.w += (v0.w + v1.w) + (v2.w + v3.w);
    }
    for (; e < end; ++e) {
        int s0 = g_esrc[e];
        float4 v0 = feat[(size_t)s0 * 64 + t];
        acc.x += v0.x; acc.y += v0.y; acc.z += v0.z; acc.w += v0.w;
    }
    float id = g_invdeg[node];
    acc.x *= id; acc.y *= id; acc.z *= id; acc.w *= id;
    __nv_bfloat16 h0, h1, h2, h3, l0, l1, l2, l3;
    split2(acc.x, h0, l0); split2(acc.y, h1, l1);
    split2(acc.z, h2, l2); split2(acc.w, h3, l3);
    uint2 hh, ll;
    hh.x = pk(h0, h1); hh.y = pk(h2, h3);
    ll.x = pk(l0, l1); ll.y = pk(l2, l3);
    ((uint2*)g_nb_hi)[(size_t)node * 64 + t] = hh;
    ((uint2*)g_nb_lo)[(size_t)node * 64 + t] = ll;
}

// ---------------- layer-1 GEMM (cp.async 2-stage, mma.sync bf16 hi/lo) ----------------
#define AST 40    // As row stride (bf16)
#define BST 136   // Bs row stride (bf16)
#define OFF_AH 0
#define OFF_AL 10240
#define OFF_BH 20480
#define OFF_BL 29184
#define ST_BYTES 37888
#define GM_SMEM (2 * ST_BYTES + 1536)   // 77312

__global__ __launch_bounds__(256) void k_gemm_mma(const float* __restrict__ bias,
                                                  const float* __restrict__ Ws2,
                                                  const float* __restrict__ Wn2) {
    extern __shared__ char dsm[];
    uint32_t sbase = s2u(dsm);
    float* sb_bias = (float*)(dsm + 2 * ST_BYTES);
    float* sb_ws = sb_bias + 128;
    float* sb_wn = sb_bias + 256;

    int tid = threadIdx.x;
    int wid = tid >> 5, lane = tid & 31;
    int brow = blockIdx.y * 128;
    int bcol = blockIdx.x * 128;
    int wm = wid & 3, wn = wid >> 2;

    if (tid < 128) {
        sb_bias[tid] = bias[bcol + tid];
        sb_ws[tid]   = Ws2[bcol + tid];
        sb_wn[tid]   = Wn2[bcol + tid];
    }

    float c[2][8][4];
#pragma unroll
    for (int mt = 0; mt < 2; ++mt)
#pragma unroll
        for (int nt = 0; nt < 8; ++nt)
#pragma unroll
            for (int j = 0; j < 4; ++j) c[mt][nt][j] = 0.f;

    // A copy mapping: (row, 16-wide k-half); B copy mapping: (k-row, 16-wide n-chunk)
    int arow = tid >> 1;
    int ak   = (tid & 1) * 16;
    int grow = brow + arow;
    if (grow >= NN) grow = NN - 1;
    int bkr = tid >> 3;
    int bnc = (tid & 7) * 16;

    uint32_t da_h = OFF_AH + (uint32_t)(arow * AST + ak) * 2;
    uint32_t da_l = OFF_AL + (uint32_t)(arow * AST + ak) * 2;
    uint32_t db_h = OFF_BH + (uint32_t)(bkr * BST + bnc) * 2;
    uint32_t db_l = OFF_BL + (uint32_t)(bkr * BST + bnc) * 2;

    auto issue = [&](int ch, int s) {
        int ka = ch * 32;
        int kaa = (ch < 8) ? ka : (ka - 256);
        const __nv_bfloat16* axh = (ch < 8) ? g_x_hi : g_nb_hi;
        const __nv_bfloat16* axl = (ch < 8) ? g_x_lo : g_nb_lo;
        uint32_t st = sbase + (uint32_t)s * ST_BYTES;
        size_t aoff = (size_t)grow * 256 + kaa + ak;
        cpa16(st + da_h,      axh + aoff);
        cpa16(st + da_h + 16, axh + aoff + 8);
        cpa16(st + da_l,      axl + aoff);
        cpa16(st + da_l + 16, axl + aoff + 8);
        size_t boff = (size_t)(ka + bkr) * 256 + bcol + bnc;
        cpa16(st + db_h,      g_wt_hi + boff);
        cpa16(st + db_h + 16, g_wt_hi + boff + 8);
        cpa16(st + db_l,      g_wt_lo + boff);
        cpa16(st + db_l + 16, g_wt_lo + boff + 8);
        CP_COMMIT();
    };

    issue(0, 0);
    issue(1, 1);

#pragma unroll 1
    for (int ch = 0; ch < 16; ++ch) {
        if (ch < 15) CP_WAIT1(); else CP_WAIT0();
        __syncthreads();

        uint32_t st = sbase + (uint32_t)(ch & 1) * ST_BYTES;
        uint32_t ahb = st + OFF_AH, alb = st + OFF_AL;
        uint32_t bhb = st + OFF_BH, blb = st + OFF_BL;

#pragma unroll
        for (int ks = 0; ks < 2; ++ks) {
            int kk = ks * 16;
            uint32_t ah[2][4], al[2][4];
#pragma unroll
            for (int mt = 0; mt < 2; ++mt) {
                int m0 = wm * 32 + mt * 16;
                uint32_t ao = (uint32_t)((m0 + (lane & 15)) * AST + kk + (lane >> 4) * 8) * 2;
                LDSM4(ah[mt], ahb + ao);
                LDSM4(al[mt], alb + ao);
            }
            uint32_t bh[8][2], bl[8][2];
#pragma unroll
            for (int nq = 0; nq < 4; ++nq) {
                int n0 = wn * 64 + nq * 16;
                uint32_t bo = (uint32_t)((kk + (lane & 15)) * BST + n0 + (lane >> 4) * 8) * 2;
                uint32_t r[4];
                LDSM4T(r, bhb + bo);
                bh[nq * 2][0] = r[0]; bh[nq * 2][1] = r[1];
                bh[nq * 2 + 1][0] = r[2]; bh[nq * 2 + 1][1] = r[3];
                LDSM4T(r, blb + bo);
                bl[nq * 2][0] = r[0]; bl[nq * 2][1] = r[1];
                bl[nq * 2 + 1][0] = r[2]; bl[nq * 2 + 1][1] = r[3];
            }
#pragma unroll
            for (int mt = 0; mt < 2; ++mt)
#pragma unroll
                for (int nt = 0; nt < 8; ++nt) {
                    mma16816(c[mt][nt], ah[mt], bh[nt]);
                    mma16816(c[mt][nt], ah[mt], bl[nt]);
                    mma16816(c[mt][nt], al[mt], bh[nt]);
                }
        }

        __syncthreads();
        if (ch + 2 < 16) issue(ch + 2, ch & 1);
    }

    // ---- fused epilogue: bias + sigmoid + dot(Ws2/Wn2) + atomic row sums ----
#pragma unroll
    for (int mt = 0; mt < 2; ++mt) {
#pragma unroll
        for (int rh = 0; rh < 2; ++rh) {
            float q = 0.f, p = 0.f;
#pragma unroll
            for (int nt = 0; nt < 8; ++nt) {
#pragma unroll
                for (int j = 0; j < 2; ++j) {
                    int lcol = wn * 64 + nt * 8 + (lane & 3) * 2 + j;
                    float v = c[mt][nt][rh * 2 + j] + sb_bias[lcol];
                    float h = 1.f / (1.f + __expf(-v));
                    q += h * sb_ws[lcol];
                    p += h * sb_wn[lcol];
                }
            }
            q += __shfl_xor_sync(0xffffffffu, q, 1);
            q += __shfl_xor_sync(0xffffffffu, q, 2);
            p += __shfl_xor_sync(0xffffffffu, p, 1);
            p += __shfl_xor_sync(0xffffffffu, p, 2);
            if ((lane & 3) == 0) {
                int row = brow + wm * 32 + mt * 16 + (lane >> 2) + rh * 8;
                if (row < NN) {
                    atomicAdd(&g_q[row], q);
                    atomicAdd(&g_p[row], p);
                }
            }
        }
    }
}

// ---------------- layer 2b: scalar mean-aggregate + combine ----------------
__global__ void k_agg_scalar(const float* __restrict__ b2, float* __restrict__ out) {
    int n = blockIdx.x * 256 + threadIdx.x;
    if (n >= NN) return;
    int beg = g_rowptr[n];
    int end = g_rowptr[n + 1];
    float s0 = 0.f, s1 = 0.f, s2 = 0.f, s3 = 0.f;
    int e = beg;
    for (; e + 3 < end; e += 4) {
        s0 += g_p[g_esrc[e]];
        s1 += g_p[g_esrc[e + 1]];
        s2 += g_p[g_esrc[e + 2]];
        s3 += g_p[g_esrc[e + 3]];
    }
    for (; e < end; ++e) s0 += g_p[g_esrc[e]];
    float s = (s0 + s1) + (s2 + s3);
    out[n] = g_q[n] + b2[0] + s * g_invdeg[n];
}

// ---------------- launch ----------------
extern "C" void kernel_launch(void* const* d_in, const int* in_sizes, int n_in,
                              void* d_out, int out_size) {
    const float* x   = (const float*)d_in[0];
    const int*   src = (const int*)d_in[1];
    const int*   dst = (const int*)d_in[2];
    const float* Ws1 = (const float*)d_in[3];
    const float* Wn1 = (const float*)d_in[4];
    const float* b1  = (const float*)d_in[5];
    const float* Ws2 = (const float*)d_in[6];
    const float* Wn2 = (const float*)d_in[7];
    const float* b2  = (const float*)d_in[8];
    float* out = (float*)d_out;

    int edgeBlocks = (NE + 255) / 256;

    cudaFuncSetAttribute(k_gemm_mma, cudaFuncAttributeMaxDynamicSharedMemorySize, GM_SMEM);

    // prep (weights + X split + zero deg/p/q)
    k_prepw<<<512, 256>>>(Ws1, Wn1);
    k_prepx<<<NN / 4, 256>>>(x);     // NN*64 threads, 4 floats each

    // CSR build
    k_hist<<<edgeBlocks, 256>>>(dst);
    k_scanA<<<NBLK, 256>>>();
    k_scanB<<<1, 512>>>(NBLK);
    k_scanC<<<NBLK, 256>>>();
    k_scatter<<<edgeBlocks, 256>>>(src, dst);

    // layer 1 aggregation (writes bf16 hi/lo)
    k_agg1<<<(NN + 3) / 4, dim3(64, 4)>>>(x);

    // layer-1 GEMM + sigmoid + fused layer-2 dots
    k_gemm_mma<<<dim3(2, (NN + 127) / 128), 256, GM_SMEM>>>(b1, Ws2, Wn2);

    // layer 2: scalar mean-aggregate + combine
    k_agg_scalar<<<NBLK, 256>>>(b2, out);
}